// round 16
// baseline (speedup 1.0000x reference)
#include <cuda_runtime.h>

// Depth-5 path signature, B=256, d=10, L=128 (127 segments).
// Output row: [S1(10) | S2(100) | S3(1000) | S4(10000) | S5(100000)] = 111110 floats.
//
// Chen recurrence with rank-1 segment tensors (increment δ):
//   P3[abc] = S3/2 + δc*(S2/6 + δb*(S1/24 + δa/120))
//   Y3[abc] = S3   + δc*(S2/2 + δb*(S1/6  + δa/24))
//   X4[abcd] = S4[abcd] + δd*P3[abc];  S4 += Y3 ⊗ δ;  S5 += X4 ⊗ δ
//   S3 += δc*(S2 + δb*(S1/2 + δa/6));  S2 += δb*(S1 + δa/2);  S1 += δ
//
// R16 = R14 (224us) with:
//   1. X4 stays PACKED into S5: s5a/s5b[e] lanes are d-pairs (half,half+2)/(half+4,
//      half+6), multiplied by broadcast (δe,δe) pairs from sdB via LDS.128 —
//      removes the per-d unpack/repack (~9 alu MOVs + 8 cyc dep chain per iter).
//      5th d (half+8) keeps adjacent-e-pair form via sdA.
//   2. Unroll x4 (PADSEG=128) for a wider cross-iteration scheduling window.
// Same 42 fma/iter; (256,2) -> 128-reg cap, expect ~112-124 regs, no spill.

#define NB 256
#define DCH 10
#define LEN 128
#define NSEG 127
#define PADSEG 128
#define THREADS 256
#define CTAS_PER_B 8
#define UNITS 2000
#define ROW 111110
#define APAD 12   // row stride: sdA/sdH in floats (48B), sdB in ulls (96B)

typedef unsigned long long ull;

__device__ __forceinline__ ull pk(float lo, float hi) {
    ull r;
    asm("mov.b64 %0, {%1, %2};" : "=l"(r) : "f"(lo), "f"(hi));
    return r;
}
__device__ __forceinline__ void upk(ull v, float& lo, float& hi) {
    asm("mov.b64 {%0, %1}, %2;" : "=f"(lo), "=f"(hi) : "l"(v));
}
__device__ __forceinline__ ull ffma2(ull a, ull b, ull c) {
    ull d;
    asm("fma.rn.f32x2 %0, %1, %2, %3;" : "=l"(d) : "l"(a), "l"(b), "l"(c));
    return d;
}

__global__ __launch_bounds__(THREADS, 2)
void sig_kernel(const float* __restrict__ path, float* __restrict__ out) {
    __shared__ __align__(16) float sdA[PADSEG * APAD];  // [t][c]: δ0..δ9 (adjacent pairs)
    __shared__ __align__(16) float sdH[PADSEG * APAD];  // [t]: evens | odds@24B
    __shared__ __align__(16) ull   sdB[PADSEG * APAD];  // [t][e] = (δe, δe) broadcasts

    const int tid = threadIdx.x;
    const int b   = blockIdx.x / CTAS_PER_B;
    const int k   = blockIdx.x % CTAS_PER_B;

    // ---- segment increments into all three layouts (+ zero pad row t=127) ----
    const float* pb = path + b * (DCH * LEN);
    for (int idx = tid; idx < NSEG * DCH; idx += THREADS) {
        int c = idx / NSEG, t = idx % NSEG;
        float d = pb[c * LEN + t + 1] - pb[c * LEN + t];
        sdA[t * APAD + c] = d;
        sdH[t * APAD + (c & 1) * 6 + (c >> 1)] = d;
        sdB[t * APAD + c] = pk(d, d);
    }
    if (tid < APAD) {
        sdA[NSEG * APAD + tid] = 0.f;
        sdH[NSEG * APAD + tid] = 0.f;
        sdB[NSEG * APAD + tid] = 0ull;
    }
    __syncthreads();

    const int u = k * THREADS + tid;
    if (u >= UNITS) return;
    const int half = u / 1000;          // this thread's d-set: {half, half+2, ..., half+8}
    const int abc  = u % 1000;
    const int a    = abc / 100;
    const int hb   = (abc / 10) % 10;
    const int hc   = abc % 10;

    float s1 = 0.f, s2 = 0.f, s3 = 0.f;   // private S1[a], S2[ab], S3[abc]
    ull   s4a = 0ull, s4b = 0ull;          // (S4[half],S4[half+2]) , (half+4,half+6)
    float s4c = 0.f;                       // S4[half+8]
    ull   s5a[10], s5b[10];                // [e]: lanes = d-pairs as in s4a/s4b
    ull   s5c[5];                          // [p]: d=half+8, lanes = (e=2p, e=2p+1)
#pragma unroll
    for (int e = 0; e < 10; ++e) { s5a[e] = 0ull; s5b[e] = 0ull; }
#pragma unroll
    for (int p = 0; p < 5; ++p) s5c[p] = 0ull;

    const float* al = sdA;
    const float* hl = sdH + half * 6;
    const ull*   blb = sdB;
    for (int t = 0; t < PADSEG; t += 4) {
#pragma unroll
        for (int w = 0; w < 4; ++w) {
            const float* alw = al + w * APAD;
            const float* hlw = hl + w * APAD;
            const ull*   blw = blb + w * APAD;

            // broadcast (δe,δe) pairs, two per LDS.128
            ulonglong2 rr0 = *(const ulonglong2*)blw;
            ulonglong2 rr1 = *(const ulonglong2*)(blw + 2);
            ulonglong2 rr2 = *(const ulonglong2*)(blw + 4);
            ulonglong2 rr3 = *(const ulonglong2*)(blw + 6);
            ulonglong2 rr4 = *(const ulonglong2*)(blw + 8);
            // adjacent e-pairs for the 5th d
            ulonglong2 e01 = *(const ulonglong2*)alw;        // (δ0,δ1)(δ2,δ3)
            ulonglong2 e23 = *(const ulonglong2*)(alw + 4);  // (δ4,δ5)(δ6,δ7)
            ull        e4  = *(const ull*)(alw + 8);         // (δ8,δ9)
            // own-half d-values as pairs
            ull   dp01  = *(const ull*)hlw;        // (δ_half, δ_{half+2})
            ull   dp23  = *(const ull*)(hlw + 2);  // (δ_{half+4}, δ_{half+6})
            float dloc4 = hlw[4];                  // δ_{half+8}
            float da = alw[a], db = alw[hb], dc = alw[hc];

            // Horner chains + private state update
            float P1 = fmaf(da, 1.f / 120.f, s1 * (1.f / 24.f));
            float P2 = fmaf(db, P1, s2 * (1.f / 6.f));
            float P3 = fmaf(dc, P2, s3 * 0.5f);
            float Q1 = fmaf(da, 1.f / 24.f, s1 * (1.f / 6.f));
            float Q2 = fmaf(db, Q1, s2 * 0.5f);
            float Y3 = fmaf(dc, Q2, s3);
            float Z1 = fmaf(da, 1.f / 6.f, s1 * 0.5f);
            float Z2 = fmaf(db, Z1, s2);
            s3 = fmaf(dc, Z2, s3);
            float W1 = fmaf(da, 0.5f, s1);
            s2 = fmaf(db, W1, s2);
            s1 += da;

            // packed X4 / S4 (X stays packed into S5 — no unpack/repack)
            ull P3p = pk(P3, P3), Y3p = pk(Y3, Y3);
            ull Xa = ffma2(dp01, P3p, s4a);  s4a = ffma2(dp01, Y3p, s4a);
            ull Xb = ffma2(dp23, P3p, s4b);  s4b = ffma2(dp23, Y3p, s4b);
            float Xc = fmaf(dloc4, P3, s4c); s4c = fmaf(dloc4, Y3, s4c);
            ull Xcp = pk(Xc, Xc);

            ull eb0 = rr0.x, eb1 = rr0.y, eb2 = rr1.x, eb3 = rr1.y, eb4 = rr2.x;
            ull eb5 = rr2.y, eb6 = rr3.x, eb7 = rr3.y, eb8 = rr4.x, eb9 = rr4.y;

            s5a[0] = ffma2(Xa, eb0, s5a[0]);  s5b[0] = ffma2(Xb, eb0, s5b[0]);
            s5a[1] = ffma2(Xa, eb1, s5a[1]);  s5b[1] = ffma2(Xb, eb1, s5b[1]);
            s5a[2] = ffma2(Xa, eb2, s5a[2]);  s5b[2] = ffma2(Xb, eb2, s5b[2]);
            s5a[3] = ffma2(Xa, eb3, s5a[3]);  s5b[3] = ffma2(Xb, eb3, s5b[3]);
            s5a[4] = ffma2(Xa, eb4, s5a[4]);  s5b[4] = ffma2(Xb, eb4, s5b[4]);
            s5a[5] = ffma2(Xa, eb5, s5a[5]);  s5b[5] = ffma2(Xb, eb5, s5b[5]);
            s5a[6] = ffma2(Xa, eb6, s5a[6]);  s5b[6] = ffma2(Xb, eb6, s5b[6]);
            s5a[7] = ffma2(Xa, eb7, s5a[7]);  s5b[7] = ffma2(Xb, eb7, s5b[7]);
            s5a[8] = ffma2(Xa, eb8, s5a[8]);  s5b[8] = ffma2(Xb, eb8, s5b[8]);
            s5a[9] = ffma2(Xa, eb9, s5a[9]);  s5b[9] = ffma2(Xb, eb9, s5b[9]);

            s5c[0] = ffma2(Xcp, e01.x, s5c[0]);
            s5c[1] = ffma2(Xcp, e01.y, s5c[1]);
            s5c[2] = ffma2(Xcp, e23.x, s5c[2]);
            s5c[3] = ffma2(Xcp, e23.y, s5c[3]);
            s5c[4] = ffma2(Xcp, e4,    s5c[4]);
        }
        al  += 4 * APAD;
        hl  += 4 * APAD;
        blb += 4 * APAD;
    }

    // ---- epilogue ----
    float* orow = out + (size_t)b * ROW;
    if (half == 0) {
        if (hb == 0 && hc == 0) orow[a] = s1;
        if (hc == 0) orow[10 + a * 10 + hb] = s2;
        orow[110 + abc] = s3;
    }
    // S4: d = half, half+2, half+4, half+6, half+8
    {
        float v0, v1, v2, v3;
        upk(s4a, v0, v1);
        upk(s4b, v2, v3);
        float* o4 = orow + 1110 + abc * 10 + half;
        o4[0] = v0; o4[2] = v1; o4[4] = v2; o4[6] = v3; o4[8] = s4c;
    }
    // S5 block of this abc: 100 floats at 11110 + abc*100, layout [d][e]
    float* o5 = orow + 11110 + abc * 100;
#pragma unroll
    for (int e = 0; e < 10; ++e) {
        float va0, va1, vb0, vb1;
        upk(s5a[e], va0, va1);
        upk(s5b[e], vb0, vb1);
        o5[(half)     * 10 + e] = va0;
        o5[(half + 2) * 10 + e] = va1;
        o5[(half + 4) * 10 + e] = vb0;
        o5[(half + 6) * 10 + e] = vb1;
    }
    {
        ull* r8 = (ull*)(o5 + (half + 8) * 10);   // (half+8)*10 even -> 8B-aligned
#pragma unroll
        for (int p = 0; p < 5; ++p) r8[p] = s5c[p];
    }
}

extern "C" void kernel_launch(void* const* d_in, const int* in_sizes, int n_in,
                              void* d_out, int out_size) {
    const float* path = (const float*)d_in[0];  // (256, 10, 128) fp32
    float* out = (float*)d_out;                 // (256, 111110) fp32
    sig_kernel<<<NB * CTAS_PER_B, THREADS>>>(path, out);
}

// round 17
// speedup vs baseline: 1.3803x; 1.3803x over previous
#include <cuda_runtime.h>

// Depth-5 path signature, B=256, d=10, L=128 (127 segments).
// Output row: [S1(10) | S2(100) | S3(1000) | S4(10000) | S5(100000)] = 111110 floats.
//
// Chen recurrence with rank-1 segment tensors (increment δ):
//   P3[abc] = S3/2 + δc*(S2/6 + δb*(S1/24 + δa/120))
//   Y3[abc] = S3   + δc*(S2/2 + δb*(S1/6  + δa/24))
//   X4[abcd] = S4[abcd] + δd*P3[abc];  S4 += Y3 ⊗ δ;  S5 += X4 ⊗ δ
//   S3 += δc*(S2 + δb*(S1/2 + δa/6));  S2 += δb*(S1 + δa/2);  S1 += δ
//
// R17 = R14 champion body (unroll x2, 110 regs, packed i-pair X4/S4, zero
// barriers) with ONLY the geometry changed: CTA = 288 threads (9 full warps),
// launch_bounds(288,2) -> reg cap 113 >= 110 natural allocation, 18 warps/SM
// (R14: 16, +12.5% issue capacity at identical instruction stream).
// 7 CTAs/batch (2016 units >= 2000, 0.8% idle), grid 1792 -> 6.05 waves.

#define NB 256
#define DCH 10
#define LEN 128
#define NSEG 127
#define PADSEG 128
#define THREADS 288
#define CTAS_PER_B 7
#define UNITS 2000
#define ROW 111110
#define APAD 12   // row stride (floats): 48B, 16B-aligned

typedef unsigned long long ull;

__device__ __forceinline__ ull pk(float lo, float hi) {
    ull r;
    asm("mov.b64 %0, {%1, %2};" : "=l"(r) : "f"(lo), "f"(hi));
    return r;
}
__device__ __forceinline__ void upk(ull v, float& lo, float& hi) {
    asm("mov.b64 {%0, %1}, %2;" : "=f"(lo), "=f"(hi) : "l"(v));
}
__device__ __forceinline__ ull ffma2(ull a, ull b, ull c) {
    ull d;
    asm("fma.rn.f32x2 %0, %1, %2, %3;" : "=l"(d) : "l"(a), "l"(b), "l"(c));
    return d;
}

__global__ __launch_bounds__(THREADS, 2)
void sig_kernel(const float* __restrict__ path, float* __restrict__ out) {
    __shared__ __align__(16) float sdA[PADSEG * APAD];  // [t][c]: δ0..δ9
    __shared__ __align__(16) float sdH[PADSEG * APAD];  // [t]: evens | odds@24B

    const int tid = threadIdx.x;
    const int b   = blockIdx.x / CTAS_PER_B;
    const int k   = blockIdx.x % CTAS_PER_B;

    // ---- segment increments into both layouts (+ zero pad row t=127) ----
    const float* pb = path + b * (DCH * LEN);
    for (int idx = tid; idx < NSEG * DCH; idx += THREADS) {
        int c = idx / NSEG, t = idx % NSEG;
        float d = pb[c * LEN + t + 1] - pb[c * LEN + t];
        sdA[t * APAD + c] = d;
        sdH[t * APAD + (c & 1) * 6 + (c >> 1)] = d;
    }
    if (tid < APAD) {
        sdA[NSEG * APAD + tid] = 0.f;
        sdH[NSEG * APAD + tid] = 0.f;
    }
    __syncthreads();

    const int u = k * THREADS + tid;
    if (u >= UNITS) return;
    const int half = u / 1000;          // d = 2*i + half
    const int abc  = u % 1000;
    const int a    = abc / 100;
    const int hb   = (abc / 10) % 10;
    const int hc   = abc % 10;

    float s1 = 0.f, s2 = 0.f, s3 = 0.f;
    ull   s4a = 0ull, s4b = 0ull;       // (S4[half],S4[2+half]) , (4+half,6+half)
    float s4c = 0.f;                    // S4[8+half]
    ull   s5[5][5];
#pragma unroll
    for (int i = 0; i < 5; ++i)
#pragma unroll
        for (int p = 0; p < 5; ++p) s5[i][p] = 0ull;

    const float* dl = sdA;
    const float* hl = sdH + half * 6;
    for (int t = 0; t < PADSEG; t += 2) {
#pragma unroll
        for (int w = 0; w < 2; ++w) {
            const float* dlw = dl + w * APAD;
            const float* hlw = hl + w * APAD;
            // e-pairs straight from the row (16B-aligned)
            ulonglong2 e01 = *(const ulonglong2*)dlw;
            ulonglong2 e23 = *(const ulonglong2*)(dlw + 4);
            ull        e4  = *(const ull*)(dlw + 8);
            // own-half d-values as pairs (8B-aligned)
            ull   dp01  = *(const ull*)hlw;
            ull   dp23  = *(const ull*)(hlw + 2);
            float dloc4 = hlw[4];
            float da = dlw[a], db = dlw[hb], dc = dlw[hc];

            // Horner chains + private state update
            float P1 = fmaf(da, 1.f / 120.f, s1 * (1.f / 24.f));
            float P2 = fmaf(db, P1, s2 * (1.f / 6.f));
            float P3 = fmaf(dc, P2, s3 * 0.5f);
            float Q1 = fmaf(da, 1.f / 24.f, s1 * (1.f / 6.f));
            float Q2 = fmaf(db, Q1, s2 * 0.5f);
            float Y3 = fmaf(dc, Q2, s3);
            float Z1 = fmaf(da, 1.f / 6.f, s1 * 0.5f);
            float Z2 = fmaf(db, Z1, s2);
            s3 = fmaf(dc, Z2, s3);
            float W1 = fmaf(da, 0.5f, s1);
            s2 = fmaf(db, W1, s2);
            s1 += da;

            // packed X4 / S4 over i-pairs
            ull P3p = pk(P3, P3), Y3p = pk(Y3, Y3);
            ull Xa = ffma2(dp01, P3p, s4a);  s4a = ffma2(dp01, Y3p, s4a);
            ull Xb = ffma2(dp23, P3p, s4b);  s4b = ffma2(dp23, Y3p, s4b);
            float Xc = fmaf(dloc4, P3, s4c); s4c = fmaf(dloc4, Y3, s4c);

            float xs0, xs1, xs2, xs3;
            upk(Xa, xs0, xs1);
            upk(Xb, xs2, xs3);
            float xs[5] = {xs0, xs1, xs2, xs3, Xc};
            ull ep[5] = {e01.x, e01.y, e23.x, e23.y, e4};

#pragma unroll
            for (int i = 0; i < 5; ++i) {
                ull X2 = pk(xs[i], xs[i]);
#pragma unroll
                for (int p = 0; p < 5; ++p)
                    s5[i][p] = ffma2(X2, ep[p], s5[i][p]);
            }
        }
        dl += 2 * APAD;
        hl += 2 * APAD;
    }

    // ---- epilogue ----
    float* orow = out + (size_t)b * ROW;
    if (half == 0) {
        if (hb == 0 && hc == 0) orow[a] = s1;
        if (hc == 0) orow[10 + a * 10 + hb] = s2;
        orow[110 + abc] = s3;
    }
    {
        float v0, v1, v2, v3;
        upk(s4a, v0, v1);
        upk(s4b, v2, v3);
        float* o4 = orow + 1110 + abc * 10 + half;
        o4[0] = v0; o4[2] = v1; o4[4] = v2; o4[6] = v3; o4[8] = s4c;
    }
    ull* o5 = (ull*)(orow + 11110);   // 8B-aligned
#pragma unroll
    for (int i = 0; i < 5; ++i) {
        int abcd = abc * 10 + 2 * i + half;
#pragma unroll
        for (int p = 0; p < 5; ++p) o5[abcd * 5 + p] = s5[i][p];
    }
}

extern "C" void kernel_launch(void* const* d_in, const int* in_sizes, int n_in,
                              void* d_out, int out_size) {
    const float* path = (const float*)d_in[0];  // (256, 10, 128) fp32
    float* out = (float*)d_out;                 // (256, 111110) fp32
    sig_kernel<<<NB * CTAS_PER_B, THREADS>>>(path, out);
}